// round 11
// baseline (speedup 1.0000x reference)
#include <cuda_runtime.h>
#include <cstdint>

#define BS 2
#define NF 16
#define C  32
#define H  128
#define W  128
#define HW (H*W)
#define NM 8
#define NK 3
#define MID (NF/2)

#define PCHUNK 128           // pixels per pool block
#define PNCH (HW/PCHUNK)     // 128 chunks
#define CG 4                 // channel groups (8 channels = 8 warps)
#define NBLK (PNCH*CG*BS)    // 1024 pool blocks

#define MPAIR 64             // pixel pairs per masks block

typedef unsigned long long ull;

// partials: row r=((b*C+c)*NM+m), PNCH floats per row (256 KB)
__device__ float g_part[BS*C*NM*PNCH];
__device__ int   g_ctr;          // zero-init; last pool block resets it

__device__ __forceinline__ ull pack2(float a, float b) {
    ull r; asm("mov.b64 %0,{%1,%2};" : "=l"(r) : "f"(a), "f"(b)); return r;
}

// ---------------------------------------------------------------------------
// Masks: grid (HW/2/MPAIR, BS) = (128, 2) = 256 blocks, 256 threads.
// thread = (pair 0..63, qc 0..3); 8 float2 loads (channels qc*8..qc*8+7),
// partials combined through smem, bias added, float2 stores.
// ---------------------------------------------------------------------------
__global__ void __launch_bounds__(256)
masks_kernel(const float* __restrict__ dec,
             const float* __restrict__ seg_w,
             const float* __restrict__ seg_b,
             float* __restrict__ masks_out)
{
    __shared__ float2 part[4][NM][MPAIR];   // 16 KB
    __shared__ float  sw[NM*C];             // 1 KB

    const int tid = threadIdx.x;
    if (tid < NM*C) sw[tid] = seg_w[tid];
    __syncthreads();

    const int b     = blockIdx.y;
    const int pair0 = blockIdx.x * MPAIR;
    const int pr    = tid & (MPAIR-1);
    const int qc    = tid >> 6;             // 0..3

    const float* src = dec + ((size_t)(b*NF + MID)*C + qc*8)*HW
                           + 2*(size_t)(pair0 + pr);
    float2 v[8];
#pragma unroll
    for (int i = 0; i < 8; i++)
        v[i] = *reinterpret_cast<const float2*>(src + (size_t)i*HW);

    float2 pm[NM];
#pragma unroll
    for (int m = 0; m < NM; m++) pm[m] = make_float2(0.f, 0.f);
#pragma unroll
    for (int i = 0; i < 8; i++)
#pragma unroll
        for (int m = 0; m < NM; m++) {
            float w = sw[m*C + qc*8 + i];
            pm[m].x += v[i].x * w;
            pm[m].y += v[i].y * w;
        }
#pragma unroll
    for (int m = 0; m < NM; m++) part[qc][m][pr] = pm[m];
    __syncthreads();

    // combine: 8 masks x 64 pairs = 512 float2 / 256 thr = 2 each
#pragma unroll
    for (int r = 0; r < 2; r++) {
        int k  = tid + r*256;
        int m  = k >> 6;
        int pp = k & (MPAIR-1);
        float2 a0 = part[0][m][pp], a1 = part[1][m][pp];
        float2 a2 = part[2][m][pp], a3 = part[3][m][pp];
        float bsc = seg_b[m];
        float2 o = make_float2(a0.x+a1.x+a2.x+a3.x + bsc,
                               a0.y+a1.y+a2.y+a3.y + bsc);
        *reinterpret_cast<float2*>(
            masks_out + ((size_t)b*NM + m)*HW + 2*(size_t)(pair0 + pp)) = o;
    }
}

// ---------------------------------------------------------------------------
// Pool + epilogue: grid (PNCH, CG, BS) = 1024 blocks, 256 thr = 8 warps.
// __launch_bounds__(256, 2): 128-reg budget so the ull accumulators + mask
// registers NEVER spill (R10's regression was a 64-reg cap spilling acc).
// Warp owns one channel; lane owns 4 px (float4).
// LAST block reduces g_part (L2-hot) -> pooled -> 48 logits.
// ---------------------------------------------------------------------------
__global__ void __launch_bounds__(256, 2)
pool_kernel(const float* __restrict__ dec,
            const float* __restrict__ masks,
            const float* __restrict__ lw,
            const float* __restrict__ lb,
            float* __restrict__ logits_out)
{
    const int tid  = threadIdx.x;
    const int wid  = tid >> 5;
    const int lane = tid & 31;

    const int ch = blockIdx.x;
    const int cg = blockIdx.y;
    const int b  = blockIdx.z;
    const int c  = cg*8 + wid;

    ull mkA[NM], mkB[NM];
#pragma unroll
    for (int m = 0; m < NM; m++) {
        float4 mv = reinterpret_cast<const float4*>(
            masks + ((size_t)b*NM + m)*HW + (size_t)ch*PCHUNK)[lane];
        mkA[m] = pack2(mv.x, mv.y);
        mkB[m] = pack2(mv.z, mv.w);
    }

    ull acc[NM];
#pragma unroll
    for (int m = 0; m < NM; m++) acc[m] = 0ULL;

    const float* base = dec + ((size_t)b*NF*C + c)*HW + (size_t)ch*PCHUNK;

#pragma unroll 4
    for (int f = 0; f < NF; f++) {
        float4 v = reinterpret_cast<const float4*>(base + (size_t)f*C*HW)[lane];
        ull v01 = pack2(v.x, v.y);
        ull v23 = pack2(v.z, v.w);
#pragma unroll
        for (int m = 0; m < NM; m++) {
            asm("fma.rn.f32x2 %0, %1, %2, %0;" : "+l"(acc[m]) : "l"(v01), "l"(mkA[m]));
            asm("fma.rn.f32x2 %0, %1, %2, %0;" : "+l"(acc[m]) : "l"(v23), "l"(mkB[m]));
        }
    }

#pragma unroll
    for (int m = 0; m < NM; m++) {
        float2 a = *reinterpret_cast<float2*>(&acc[m]);
        float s = a.x + a.y;
#pragma unroll
        for (int off = 16; off; off >>= 1)
            s += __shfl_xor_sync(0xffffffffu, s, off);
        if (lane == 0)
            g_part[(((size_t)b*C + c)*NM + m)*PNCH + ch] = s;
    }

    // ---- epilogue: last block reduces partials + computes logits ----
    __shared__ bool is_last;
    __syncthreads();
    if (tid == 0) {
        __threadfence();
        is_last = (atomicAdd(&g_ctr, 1) == NBLK - 1);
    }
    __syncthreads();
    if (!is_last) return;

    __threadfence();                      // acquire all g_part writes
    __shared__ float pooled[BS*NM*C];     // 2 KB

    // 512 rows / 256 threads = 2 rows each; low-register loop (no unroll blowup)
#pragma unroll 1
    for (int r = 0; r < 2; r++) {
        int row = tid*2 + r;
        const float4* src = reinterpret_cast<const float4*>(
            g_part + (size_t)row*PNCH);
        float s = 0.f;
#pragma unroll 2
        for (int q = 0; q < PNCH/4; q++) {
            float4 a = src[q];
            s += (a.x + a.y) + (a.z + a.w);
        }
        int m  = row & (NM-1);
        int c2 = (row / NM) & (C-1);
        int b2 = row / (NM*C);
        pooled[((size_t)b2*NM + m)*C + c2] = s * (1.0f / NF);
    }
    __syncthreads();

    if (tid < BS*NM*NK) {
        int k  = tid % NK;
        int bm = tid / NK;
        const float* p = pooled + (size_t)bm*C;
        float acc2 = lb[k];
#pragma unroll 1
        for (int c2 = 0; c2 < C; c2++) acc2 += p[c2] * lw[k*C + c2];
        logits_out[tid] = acc2;
    }
    if (tid == 0) g_ctr = 0;              // reset for next graph replay
}

// ---------------------------------------------------------------------------
extern "C" void kernel_launch(void* const* d_in, const int* in_sizes, int n_in,
                              void* d_out, int out_size)
{
    const float* dec   = (const float*)d_in[0];
    const float* seg_w = (const float*)d_in[1];
    const float* seg_b = (const float*)d_in[2];
    const float* lw    = (const float*)d_in[3];
    const float* lb    = (const float*)d_in[4];

    float* out    = (float*)d_out;
    float* logits = out;                 // 48 floats
    float* masks  = out + BS*NM*NK;      // 262144 floats

    masks_kernel<<<dim3(HW/2/MPAIR, BS), 256>>>(dec, seg_w, seg_b, masks);
    pool_kernel <<<dim3(PNCH, CG, BS), 256>>>(dec, masks, lw, lb, logits);
}

// round 12
// speedup vs baseline: 1.0767x; 1.0767x over previous
#include <cuda_runtime.h>
#include <cstdint>

#define BS 2
#define NF 16
#define C  32
#define H  128
#define W  128
#define HW (H*W)
#define NM 8
#define NK 3
#define MID (NF/2)

#define PCHUNK 128           // pixels per pool block
#define PNCH (HW/PCHUNK)     // 128 chunks
#define CG 4                 // channel groups (8 channels = 8 warps)
#define NBLK (PNCH*CG*BS)    // 1024 pool blocks

#define MPAIR 64             // pixel pairs per masks block

typedef unsigned long long ull;

// partials: row r=((b*C+c)*NM+m), PNCH floats per row (256 KB)
__device__ float g_part[BS*C*NM*PNCH];
__device__ int   g_ctr;          // zero-init; last pool block resets it

__device__ __forceinline__ ull pack2(float a, float b) {
    ull r; asm("mov.b64 %0,{%1,%2};" : "=l"(r) : "f"(a), "f"(b)); return r;
}

// ---------------------------------------------------------------------------
// Masks: grid (HW/2/MPAIR, BS) = (128, 2) = 256 blocks, 256 threads.
// ---------------------------------------------------------------------------
__global__ void __launch_bounds__(256)
masks_kernel(const float* __restrict__ dec,
             const float* __restrict__ seg_w,
             const float* __restrict__ seg_b,
             float* __restrict__ masks_out)
{
    __shared__ float2 part[4][NM][MPAIR];   // 16 KB
    __shared__ float  sw[NM*C];             // 1 KB

    const int tid = threadIdx.x;
    if (tid < NM*C) sw[tid] = seg_w[tid];
    __syncthreads();

    const int b     = blockIdx.y;
    const int pair0 = blockIdx.x * MPAIR;
    const int pr    = tid & (MPAIR-1);
    const int qc    = tid >> 6;             // 0..3

    const float* src = dec + ((size_t)(b*NF + MID)*C + qc*8)*HW
                           + 2*(size_t)(pair0 + pr);
    float2 v[8];
#pragma unroll
    for (int i = 0; i < 8; i++)
        v[i] = *reinterpret_cast<const float2*>(src + (size_t)i*HW);

    float2 pm[NM];
#pragma unroll
    for (int m = 0; m < NM; m++) pm[m] = make_float2(0.f, 0.f);
#pragma unroll
    for (int i = 0; i < 8; i++)
#pragma unroll
        for (int m = 0; m < NM; m++) {
            float w = sw[m*C + qc*8 + i];
            pm[m].x += v[i].x * w;
            pm[m].y += v[i].y * w;
        }
#pragma unroll
    for (int m = 0; m < NM; m++) part[qc][m][pr] = pm[m];
    __syncthreads();

#pragma unroll
    for (int r = 0; r < 2; r++) {
        int k  = tid + r*256;
        int m  = k >> 6;
        int pp = k & (MPAIR-1);
        float2 a0 = part[0][m][pp], a1 = part[1][m][pp];
        float2 a2 = part[2][m][pp], a3 = part[3][m][pp];
        float bsc = seg_b[m];
        float2 o = make_float2(a0.x+a1.x+a2.x+a3.x + bsc,
                               a0.y+a1.y+a2.y+a3.y + bsc);
        *reinterpret_cast<float2*>(
            masks_out + ((size_t)b*NM + m)*HW + 2*(size_t)(pair0 + pp)) = o;
    }
}

// ---------------------------------------------------------------------------
// Pool + epilogue: grid (PNCH, CG, BS) = 1024 blocks, 256 thr = 8 warps.
// Software-pipelined loads: 4-frame groups double-buffered so 4-8 LDG.128
// stay in flight per warp (R11 showed unroll-pragma alone gave MLP~1-2).
// ---------------------------------------------------------------------------
__global__ void __launch_bounds__(256)
pool_kernel(const float* __restrict__ dec,
            const float* __restrict__ masks,
            const float* __restrict__ lw,
            const float* __restrict__ lb,
            float* __restrict__ logits_out)
{
    const int tid  = threadIdx.x;
    const int wid  = tid >> 5;
    const int lane = tid & 31;

    const int ch = blockIdx.x;
    const int cg = blockIdx.y;
    const int b  = blockIdx.z;
    const int c  = cg*8 + wid;

    ull mkA[NM], mkB[NM];
#pragma unroll
    for (int m = 0; m < NM; m++) {
        float4 mv = reinterpret_cast<const float4*>(
            masks + ((size_t)b*NM + m)*HW + (size_t)ch*PCHUNK)[lane];
        mkA[m] = pack2(mv.x, mv.y);
        mkB[m] = pack2(mv.z, mv.w);
    }

    ull acc[NM];
#pragma unroll
    for (int m = 0; m < NM; m++) acc[m] = 0ULL;

    const float* base = dec + ((size_t)b*NF*C + c)*HW + (size_t)ch*PCHUNK;

    // ---- pipelined mainloop: groups of 4 frames, double-buffered ----
    float4 cur[4], nxt[4];
#pragma unroll
    for (int i = 0; i < 4; i++)
        cur[i] = reinterpret_cast<const float4*>(base + (size_t)i*C*HW)[lane];

#pragma unroll
    for (int g = 0; g < 4; g++) {
        if (g < 3) {
#pragma unroll
            for (int i = 0; i < 4; i++)
                nxt[i] = reinterpret_cast<const float4*>(
                    base + (size_t)((g+1)*4 + i)*C*HW)[lane];
        }
#pragma unroll
        for (int i = 0; i < 4; i++) {
            ull v01 = pack2(cur[i].x, cur[i].y);
            ull v23 = pack2(cur[i].z, cur[i].w);
#pragma unroll
            for (int m = 0; m < NM; m++) {
                asm("fma.rn.f32x2 %0, %1, %2, %0;" : "+l"(acc[m]) : "l"(v01), "l"(mkA[m]));
                asm("fma.rn.f32x2 %0, %1, %2, %0;" : "+l"(acc[m]) : "l"(v23), "l"(mkB[m]));
            }
        }
#pragma unroll
        for (int i = 0; i < 4; i++) cur[i] = nxt[i];
    }

#pragma unroll
    for (int m = 0; m < NM; m++) {
        float2 a = *reinterpret_cast<float2*>(&acc[m]);
        float s = a.x + a.y;
#pragma unroll
        for (int off = 16; off; off >>= 1)
            s += __shfl_xor_sync(0xffffffffu, s, off);
        if (lane == 0)
            g_part[(((size_t)b*C + c)*NM + m)*PNCH + ch] = s;
    }

    // ---- epilogue: last block reduces partials + computes logits ----
    __shared__ bool is_last;
    __syncthreads();
    if (tid == 0) {
        __threadfence();
        is_last = (atomicAdd(&g_ctr, 1) == NBLK - 1);
    }
    __syncthreads();
    if (!is_last) return;

    __threadfence();                      // acquire all g_part writes
    __shared__ float pooled[BS*NM*C];     // 2 KB

    // 512 rows / 256 threads = 2 rows each; unroll 8 -> MLP 8 per thread
#pragma unroll 1
    for (int r = 0; r < 2; r++) {
        int row = tid*2 + r;
        const float4* src = reinterpret_cast<const float4*>(
            g_part + (size_t)row*PNCH);
        float s = 0.f;
#pragma unroll 8
        for (int q = 0; q < PNCH/4; q++) {
            float4 a = src[q];
            s += (a.x + a.y) + (a.z + a.w);
        }
        int m  = row & (NM-1);
        int c2 = (row / NM) & (C-1);
        int b2 = row / (NM*C);
        pooled[((size_t)b2*NM + m)*C + c2] = s * (1.0f / NF);
    }
    __syncthreads();

    if (tid < BS*NM*NK) {
        int k  = tid % NK;
        int bm = tid / NK;
        const float* p = pooled + (size_t)bm*C;
        float acc2 = lb[k];
#pragma unroll 1
        for (int c2 = 0; c2 < C; c2++) acc2 += p[c2] * lw[k*C + c2];
        logits_out[tid] = acc2;
    }
    if (tid == 0) g_ctr = 0;              // reset for next graph replay
}

// ---------------------------------------------------------------------------
extern "C" void kernel_launch(void* const* d_in, const int* in_sizes, int n_in,
                              void* d_out, int out_size)
{
    const float* dec   = (const float*)d_in[0];
    const float* seg_w = (const float*)d_in[1];
    const float* seg_b = (const float*)d_in[2];
    const float* lw    = (const float*)d_in[3];
    const float* lb    = (const float*)d_in[4];

    float* out    = (float*)d_out;
    float* logits = out;                 // 48 floats
    float* masks  = out + BS*NM*NK;      // 262144 floats

    masks_kernel<<<dim3(HW/2/MPAIR, BS), 256>>>(dec, seg_w, seg_b, masks);
    pool_kernel <<<dim3(PNCH, CG, BS), 256>>>(dec, masks, lw, lb, logits);
}

// round 13
// speedup vs baseline: 1.5200x; 1.4117x over previous
#include <cuda_runtime.h>
#include <cstdint>

#define BS 2
#define NF 16
#define C  32
#define H  128
#define W  128
#define HW (H*W)
#define NM 8
#define NK 3
#define MID (NF/2)

#define PCHUNK 128           // pixels per pool block
#define PNCH (HW/PCHUNK)     // 128 chunks
#define CG 4                 // channel groups (8 channels = 8 warps)

#define MPAIR 64             // pixel pairs per masks block

typedef unsigned long long ull;

// partials: [b][c][m][ch]  (rows of PNCH = 128 floats, 256 KB total)
__device__ float g_part[BS*C*NM*PNCH];
__device__ float g_pooled[BS*NM*C];
__device__ int   g_ctr;          // zero-initialized; self-resets each launch

__device__ __forceinline__ ull pack2(float a, float b) {
    ull r; asm("mov.b64 %0,{%1,%2};" : "=l"(r) : "f"(a), "f"(b)); return r;
}

// ---------------------------------------------------------------------------
// Masks (R10-validated fast version): grid (HW/2/MPAIR, BS) = 256 blocks,
// 256 threads. thread = (pair 0..63, qc 0..3); 8 float2 loads (MLP 8),
// partials combined through smem, bias added, float2 stores.
// ---------------------------------------------------------------------------
__global__ void __launch_bounds__(256)
masks_kernel(const float* __restrict__ dec,
             const float* __restrict__ seg_w,
             const float* __restrict__ seg_b,
             float* __restrict__ masks_out)
{
    __shared__ float2 part[4][NM][MPAIR];   // 16 KB
    __shared__ float  sw[NM*C];             // 1 KB

    const int tid = threadIdx.x;
    if (tid < NM*C) sw[tid] = seg_w[tid];
    __syncthreads();

    const int b     = blockIdx.y;
    const int pair0 = blockIdx.x * MPAIR;
    const int pr    = tid & (MPAIR-1);
    const int qc    = tid >> 6;             // 0..3

    const float* src = dec + ((size_t)(b*NF + MID)*C + qc*8)*HW
                           + 2*(size_t)(pair0 + pr);
    float2 v[8];
#pragma unroll
    for (int i = 0; i < 8; i++)
        v[i] = *reinterpret_cast<const float2*>(src + (size_t)i*HW);

    float2 pm[NM];
#pragma unroll
    for (int m = 0; m < NM; m++) pm[m] = make_float2(0.f, 0.f);
#pragma unroll
    for (int i = 0; i < 8; i++)
#pragma unroll
        for (int m = 0; m < NM; m++) {
            float w = sw[m*C + qc*8 + i];
            pm[m].x += v[i].x * w;
            pm[m].y += v[i].y * w;
        }
#pragma unroll
    for (int m = 0; m < NM; m++) part[qc][m][pr] = pm[m];
    __syncthreads();

    // combine: 8 masks x 64 pairs = 512 float2 / 256 thr = 2 each
#pragma unroll
    for (int r = 0; r < 2; r++) {
        int k  = tid + r*256;
        int m  = k >> 6;
        int pp = k & (MPAIR-1);
        float2 a0 = part[0][m][pp], a1 = part[1][m][pp];
        float2 a2 = part[2][m][pp], a3 = part[3][m][pp];
        float bsc = seg_b[m];
        float2 o = make_float2(a0.x+a1.x+a2.x+a3.x + bsc,
                               a0.y+a1.y+a2.y+a3.y + bsc);
        *reinterpret_cast<float2*>(
            masks_out + ((size_t)b*NM + m)*HW + 2*(size_t)(pair0 + pp)) = o;
    }
}

// ---------------------------------------------------------------------------
// Pool (K6 verbatim — the 18.9us run's codegen): grid (PNCH, CG, BS) = 1024
// blocks, 256 thr = 8 warps. Warp owns one channel; lane owns 4 px (float4).
// ---------------------------------------------------------------------------
__global__ void __launch_bounds__(256)
pool_kernel(const float* __restrict__ dec, const float* __restrict__ masks)
{
    const int tid  = threadIdx.x;
    const int wid  = tid >> 5;
    const int lane = tid & 31;

    const int ch = blockIdx.x;
    const int cg = blockIdx.y;
    const int b  = blockIdx.z;
    const int c  = cg*8 + wid;

    ull mkA[NM], mkB[NM];
#pragma unroll
    for (int m = 0; m < NM; m++) {
        float4 mv = reinterpret_cast<const float4*>(
            masks + ((size_t)b*NM + m)*HW + (size_t)ch*PCHUNK)[lane];
        mkA[m] = pack2(mv.x, mv.y);
        mkB[m] = pack2(mv.z, mv.w);
    }

    ull acc[NM];
#pragma unroll
    for (int m = 0; m < NM; m++) acc[m] = 0ULL;

    const float* base = dec + ((size_t)b*NF*C + c)*HW + (size_t)ch*PCHUNK;

#pragma unroll 4
    for (int f = 0; f < NF; f++) {
        float4 v = reinterpret_cast<const float4*>(base + (size_t)f*C*HW)[lane];
        ull v01 = pack2(v.x, v.y);
        ull v23 = pack2(v.z, v.w);
#pragma unroll
        for (int m = 0; m < NM; m++) {
            asm("fma.rn.f32x2 %0, %1, %2, %0;" : "+l"(acc[m]) : "l"(v01), "l"(mkA[m]));
            asm("fma.rn.f32x2 %0, %1, %2, %0;" : "+l"(acc[m]) : "l"(v23), "l"(mkB[m]));
        }
    }

#pragma unroll
    for (int m = 0; m < NM; m++) {
        float2 a = *reinterpret_cast<float2*>(&acc[m]);
        float s = a.x + a.y;
#pragma unroll
        for (int off = 16; off; off >>= 1)
            s += __shfl_xor_sync(0xffffffffu, s, off);
        if (lane == 0)
            g_part[(((size_t)b*C + c)*NM + m)*PNCH + ch] = s;
    }
}

// ---------------------------------------------------------------------------
// Reduce + logits (K6 verbatim): 512 blocks x 128 thr; block reduces one
// (b,c,m) row of 128 floats; the LAST block computes the 48 logits.
// ---------------------------------------------------------------------------
__global__ void __launch_bounds__(128)
reduce_logits_kernel(const float* __restrict__ lw,
                     const float* __restrict__ lb,
                     float* __restrict__ out)
{
    const int row = blockIdx.x;            // (b*C + c)*NM + m
    const int tid = threadIdx.x;

    float s = g_part[(size_t)row*PNCH + tid];
#pragma unroll
    for (int off = 16; off; off >>= 1)
        s += __shfl_xor_sync(0xffffffffu, s, off);

    __shared__ float ws[4];
    __shared__ bool  is_last;
    if ((tid & 31) == 0) ws[tid >> 5] = s;
    __syncthreads();

    if (tid == 0) {
        float t = (ws[0] + ws[1] + ws[2] + ws[3]) * (1.0f / NF);
        int m = row & (NM-1);
        int c = (row / NM) & (C-1);
        int b = row / (NM*C);
        g_pooled[((size_t)b*NM + m)*C + c] = t;
        __threadfence();
        is_last = (atomicAdd(&g_ctr, 1) == gridDim.x - 1);
    }
    __syncthreads();

    if (is_last) {
        __threadfence();                   // acquire pooled writes
        if (tid < BS*NM*NK) {
            int k  = tid % NK;
            int bm = tid / NK;
            const float* p = g_pooled + (size_t)bm*C;
            float acc = lb[k];
#pragma unroll
            for (int c = 0; c < C; c++) acc += p[c] * lw[k*C + c];
            out[tid] = acc;
        }
        if (tid == 0) g_ctr = 0;           // reset for next graph replay
    }
}

// ---------------------------------------------------------------------------
extern "C" void kernel_launch(void* const* d_in, const int* in_sizes, int n_in,
                              void* d_out, int out_size)
{
    const float* dec   = (const float*)d_in[0];
    const float* seg_w = (const float*)d_in[1];
    const float* seg_b = (const float*)d_in[2];
    const float* lw    = (const float*)d_in[3];
    const float* lb    = (const float*)d_in[4];

    float* out    = (float*)d_out;
    float* logits = out;                 // 48 floats
    float* masks  = out + BS*NM*NK;      // 262144 floats

    masks_kernel        <<<dim3(HW/2/MPAIR, BS), 256>>>(dec, seg_w, seg_b, masks);
    pool_kernel         <<<dim3(PNCH, CG, BS), 256>>>(dec, masks);
    reduce_logits_kernel<<<BS*C*NM, 128>>>(lw, lb, logits);
}